// round 3
// baseline (speedup 1.0000x reference)
#include <cuda_runtime.h>
#include <cuda_bf16.h>
#include <cstdint>

// Problem constants (fixed by the dataset)
constexpr int NN  = 100000;   // nodes
constexpr int EE  = 1600000;  // edges
constexpr int GG  = 256;      // graphs
constexpr int DIN = 64;
constexpr int HID = 128;

// Scratch (device globals — no allocation allowed)
__device__ float g_agg[(size_t)NN * HID];
__device__ float g_tmp[(size_t)NN * HID];
__device__ float g_h1 [(size_t)NN * HID];
__device__ float g_h2 [(size_t)NN * HID];
__device__ float g_gsum[GG];
__device__ float g_gcnt[GG];

// ---------------------------------------------------------------------------
// Vector global reduction (sm_90+): 16B atomic add, 4x fewer L2 atomic ops
// ---------------------------------------------------------------------------
__device__ __forceinline__ void red_add_v4(float* p, float4 v) {
    asm volatile("red.global.add.v4.f32 [%0], {%1,%2,%3,%4};"
                 :: "l"(p), "f"(v.x), "f"(v.y), "f"(v.z), "f"(v.w) : "memory");
}

// ---------------------------------------------------------------------------
// float4 copy: dst[i] = src[i]
// ---------------------------------------------------------------------------
__global__ void copy_f4(float4* __restrict__ dst, const float4* __restrict__ src, int n4) {
    int t = blockIdx.x * blockDim.x + threadIdx.x;
    if (t < n4) dst[t] = src[t];
}

// ---------------------------------------------------------------------------
// Scatter-add: agg[dst[e]] += x[src[e]], D floats per node, D/4 float4 lanes.
// One thread per (edge, float4-chunk). Indices are INT32 (JAX default x64 off).
// ---------------------------------------------------------------------------
template <int D>
__global__ void scatter_add(const float* __restrict__ x,
                            const int* __restrict__ src,
                            const int* __restrict__ dst,
                            float* __restrict__ agg) {
    constexpr int C  = D / 4;                 // float4 chunks per node (16 or 32)
    long long t = (long long)blockIdx.x * blockDim.x + threadIdx.x;
    if (t >= (long long)EE * C) return;
    int e = (int)(t / C);
    int c = (int)(t - (long long)e * C);
    int s = __ldg(&src[e]);
    int d = __ldg(&dst[e]);
    float4 v = __ldg((const float4*)(x + (size_t)s * D) + c);
    red_add_v4(agg + (size_t)d * D + (size_t)c * 4, v);
}

// ---------------------------------------------------------------------------
// Fused GEMM + bias + ReLU:  out[N,128] = relu(A[N,K] @ W[K,128] + b)
// Block: 256 threads = 32 col-groups (4 cols each, LDS.128 on W) x 8 row-groups
// (4 rows each). Tile = 32 rows. W + bias + input tile staged in dynamic SMEM.
// Persistent blocks so W is loaded from L2 once per block, not per tile.
// N must be divisible by 32 (100000 = 3125 * 32).
// ---------------------------------------------------------------------------
template <int K>
__global__ __launch_bounds__(256, 2) void gemm_bias_relu(
    const float* __restrict__ A, const float* __restrict__ W,
    const float* __restrict__ bias, float* __restrict__ out, int ntiles)
{
    extern __shared__ float smem[];
    float* sW  = smem;                 // K*128
    float* sB  = smem + K * 128;       // 128
    float* sIn = sB + 128;             // 32*K

    // Stage weights + bias
    for (int i = threadIdx.x; i < K * 32; i += 256)
        ((float4*)sW)[i] = ((const float4*)W)[i];
    if (threadIdx.x < 128) sB[threadIdx.x] = bias[threadIdx.x];
    __syncthreads();

    const int cg = threadIdx.x & 31;   // column group: cols [4cg, 4cg+4)
    const int rg = threadIdx.x >> 5;   // row group:    rows [4rg, 4rg+4) in tile

    float4 bb = ((const float4*)sB)[cg];

    for (int tile = blockIdx.x; tile < ntiles; tile += gridDim.x) {
        // Stage 32 input rows (contiguous in A) into SMEM
        const float4* srcv = (const float4*)(A + (size_t)tile * 32 * K);
        for (int i = threadIdx.x; i < 32 * K / 4; i += 256)
            ((float4*)sIn)[i] = srcv[i];
        __syncthreads();

        float acc[4][4];
        #pragma unroll
        for (int j = 0; j < 4; j++)
            #pragma unroll
            for (int c = 0; c < 4; c++) acc[j][c] = 0.f;

        #pragma unroll 4
        for (int k = 0; k < K; k++) {
            float4 w = ((const float4*)(sW + k * 128))[cg];   // LDS.128, conflict-free
            float i0 = sIn[(rg * 4 + 0) * K + k];              // broadcast LDS
            float i1 = sIn[(rg * 4 + 1) * K + k];
            float i2 = sIn[(rg * 4 + 2) * K + k];
            float i3 = sIn[(rg * 4 + 3) * K + k];
            acc[0][0] += i0 * w.x; acc[0][1] += i0 * w.y; acc[0][2] += i0 * w.z; acc[0][3] += i0 * w.w;
            acc[1][0] += i1 * w.x; acc[1][1] += i1 * w.y; acc[1][2] += i1 * w.z; acc[1][3] += i1 * w.w;
            acc[2][0] += i2 * w.x; acc[2][1] += i2 * w.y; acc[2][2] += i2 * w.z; acc[2][3] += i2 * w.w;
            acc[3][0] += i3 * w.x; acc[3][1] += i3 * w.y; acc[3][2] += i3 * w.z; acc[3][3] += i3 * w.w;
        }

        #pragma unroll
        for (int j = 0; j < 4; j++) {
            int row = tile * 32 + rg * 4 + j;
            float4 o;
            o.x = fmaxf(acc[j][0] + bb.x, 0.f);
            o.y = fmaxf(acc[j][1] + bb.y, 0.f);
            o.z = fmaxf(acc[j][2] + bb.z, 0.f);
            o.w = fmaxf(acc[j][3] + bb.w, 0.f);
            ((float4*)(out + (size_t)row * 128))[cg] = o;
        }
        __syncthreads();  // before next tile overwrites sIn
    }
}

// ---------------------------------------------------------------------------
// Zero the tiny pooling accumulators
// ---------------------------------------------------------------------------
__global__ void zero_pool() {
    int t = threadIdx.x;
    if (t < GG) { g_gsum[t] = 0.f; g_gcnt[t] = 0.f; }
}

// ---------------------------------------------------------------------------
// Pool: per-node dot(h2[i], Wfc) scattered into per-graph sums (linearity of
// mean-pool + FC). One warp per node. batch is INT32.
// ---------------------------------------------------------------------------
__global__ void pool_dot(const float* __restrict__ h,
                         const float* __restrict__ Wfc,
                         const int* __restrict__ batch) {
    __shared__ float sw[128];
    if (threadIdx.x < 128) sw[threadIdx.x] = Wfc[threadIdx.x];
    __syncthreads();
    int gw    = (blockIdx.x * blockDim.x + threadIdx.x) >> 5;
    int lane  = threadIdx.x & 31;
    int nwarp = (gridDim.x * blockDim.x) >> 5;
    for (int node = gw; node < NN; node += nwarp) {
        float4 v = ((const float4*)(h + (size_t)node * 128))[lane];
        float4 w = ((const float4*)sw)[lane];
        float p = v.x * w.x + v.y * w.y + v.z * w.z + v.w * w.w;
        #pragma unroll
        for (int o = 16; o > 0; o >>= 1) p += __shfl_down_sync(0xffffffffu, p, o);
        if (lane == 0) {
            int b = __ldg(&batch[node]);
            atomicAdd(&g_gsum[b], p);
            atomicAdd(&g_gcnt[b], 1.0f);
        }
    }
}

__global__ void finalize(float* __restrict__ out, const float* __restrict__ bfc) {
    int t = threadIdx.x;
    if (t < GG) out[t] = g_gsum[t] / fmaxf(g_gcnt[t], 1.0f) + bfc[0];
}

// ---------------------------------------------------------------------------
extern "C" void kernel_launch(void* const* d_in, const int* in_sizes, int n_in,
                              void* d_out, int out_size) {
    const float* x     = (const float*)d_in[0];
    const int*   ei    = (const int*)d_in[1];     // int32 (JAX default x64 disabled)
    const int*   batch = (const int*)d_in[2];     // int32
    const float* W1a = (const float*)d_in[3];
    const float* b1a = (const float*)d_in[4];
    const float* W1b = (const float*)d_in[5];
    const float* b1b = (const float*)d_in[6];
    const float* W2a = (const float*)d_in[7];
    const float* b2a = (const float*)d_in[8];
    const float* W2b = (const float*)d_in[9];
    const float* b2b = (const float*)d_in[10];
    const float* Wfc = (const float*)d_in[11];
    const float* bfc = (const float*)d_in[12];
    float* out = (float*)d_out;

    const int* esrc = ei;
    const int* edst = ei + EE;

    float *agg, *tmp, *h1, *h2;
    cudaGetSymbolAddress((void**)&agg, g_agg);
    cudaGetSymbolAddress((void**)&tmp, g_tmp);
    cudaGetSymbolAddress((void**)&h1,  g_h1);
    cudaGetSymbolAddress((void**)&h2,  g_h2);

    const int smem64  = (64  * 128 + 128 + 32 * 64 ) * 4;   // ~41.5 KB
    const int smem128 = (128 * 128 + 128 + 32 * 128) * 4;   // ~82.4 KB
    cudaFuncSetAttribute(gemm_bias_relu<64>,  cudaFuncAttributeMaxDynamicSharedMemorySize, smem64);
    cudaFuncSetAttribute(gemm_bias_relu<128>, cudaFuncAttributeMaxDynamicSharedMemorySize, smem128);

    const int ntiles = NN / 32;          // 3125
    const int ggrid  = 296;              // ~2 blocks/SM persistent

    // ---- Layer 1 ----
    // agg := x  (so agg accumulates x + sum of neighbors)
    {
        int n4 = NN * DIN / 4;
        copy_f4<<<(n4 + 255) / 256, 256>>>((float4*)agg, (const float4*)x, n4);
    }
    {
        long long total = (long long)EE * (DIN / 4);
        int blocks = (int)((total + 255) / 256);
        scatter_add<DIN><<<blocks, 256>>>(x, esrc, edst, agg);
    }
    gemm_bias_relu<64> <<<ggrid, 256, smem64 >>>(agg, W1a, b1a, tmp, ntiles);
    gemm_bias_relu<128><<<ggrid, 256, smem128>>>(tmp, W1b, b1b, h1,  ntiles);

    // ---- Layer 2 ----
    {
        int n4 = NN * HID / 4;
        copy_f4<<<(n4 + 255) / 256, 256>>>((float4*)agg, (const float4*)h1, n4);
    }
    {
        long long total = (long long)EE * (HID / 4);
        int blocks = (int)((total + 255) / 256);
        scatter_add<HID><<<blocks, 256>>>(h1, esrc, edst, agg);
    }
    gemm_bias_relu<128><<<ggrid, 256, smem128>>>(agg, W2a, b2a, tmp, ntiles);
    gemm_bias_relu<128><<<ggrid, 256, smem128>>>(tmp, W2b, b2b, h2,  ntiles);

    // ---- Pool + FC ----
    zero_pool<<<1, 256>>>();
    pool_dot<<<512, 256>>>(h2, Wfc, batch);
    finalize<<<1, 256>>>(out, bfc);
}

// round 4
// speedup vs baseline: 1.1437x; 1.1437x over previous
#include <cuda_runtime.h>
#include <cuda_bf16.h>
#include <cstdint>

// Problem constants (fixed by the dataset)
constexpr int NN  = 100000;   // nodes
constexpr int EE  = 1600000;  // edges
constexpr int GG  = 256;      // graphs
constexpr int DIN = 64;
constexpr int HID = 128;

// Scratch (device globals — no allocation allowed)
__device__ float g_agg[(size_t)NN * HID];
__device__ float g_tmp[(size_t)NN * HID];
__device__ float g_h1 [(size_t)NN * HID];
__device__ float g_h2 [(size_t)NN * HID];
__device__ float g_gsum[GG];
__device__ float g_gcnt[GG];

// ---------------------------------------------------------------------------
// Vector global reduction (sm_90+): 16B atomic add, 4x fewer L2 atomic ops
// ---------------------------------------------------------------------------
__device__ __forceinline__ void red_add_v4(float* p, float4 v) {
    asm volatile("red.global.add.v4.f32 [%0], {%1,%2,%3,%4};"
                 :: "l"(p), "f"(v.x), "f"(v.y), "f"(v.z), "f"(v.w) : "memory");
}

// ---------------------------------------------------------------------------
// float4 copy: dst[i] = src[i]
// ---------------------------------------------------------------------------
__global__ void copy_f4(float4* __restrict__ dst, const float4* __restrict__ src, int n4) {
    int t = blockIdx.x * blockDim.x + threadIdx.x;
    if (t < n4) dst[t] = src[t];
}

// ---------------------------------------------------------------------------
// Scatter-add: agg[dst[e]] += x[src[e]], D floats per node, D/4 float4 lanes.
// One thread per (edge, float4-chunk). Indices are INT32.
// ---------------------------------------------------------------------------
template <int D>
__global__ void scatter_add(const float* __restrict__ x,
                            const int* __restrict__ src,
                            const int* __restrict__ dst,
                            float* __restrict__ agg) {
    constexpr int C  = D / 4;                 // float4 chunks per node (16 or 32)
    long long t = (long long)blockIdx.x * blockDim.x + threadIdx.x;
    if (t >= (long long)EE * C) return;
    int e = (int)(t / C);
    int c = (int)(t - (long long)e * C);
    int s = __ldg(&src[e]);
    int d = __ldg(&dst[e]);
    float4 v = __ldg((const float4*)(x + (size_t)s * D) + c);
    red_add_v4(agg + (size_t)d * D + (size_t)c * 4, v);
}

// ---------------------------------------------------------------------------
// Fused GEMM + bias + ReLU:  out[N,128] = relu(A[N,K] @ W[K,128] + b)
// 256 threads. Tile = 64 rows x 128 cols. Thread tile = 8 rows x 4 cols.
//   cg = tid & 31  -> cols [4cg, 4cg+4)   (W via LDS.128, conflict-free)
//   rg = tid >> 5  -> rows [8rg, 8rg+8)   (inputs via broadcast LDS.128)
// k unrolled by 4 (float4 input loads): per k4-step, 12 LDS.128 per 128 FMAs.
// W + bias + 64-row input tile staged in SMEM; persistent blocks.
// ---------------------------------------------------------------------------
template <int K>
__global__ __launch_bounds__(256, 2) void gemm_bias_relu(
    const float* __restrict__ A, const float* __restrict__ W,
    const float* __restrict__ bias, float* __restrict__ out, int ntiles)
{
    extern __shared__ float smem[];
    float* sW  = smem;                  // K*128 floats
    float* sIn = smem + K * 128;        // 64*K floats
    __shared__ float sB[128];

    for (int i = threadIdx.x; i < K * 32; i += 256)
        ((float4*)sW)[i] = ((const float4*)W)[i];
    if (threadIdx.x < 128) sB[threadIdx.x] = bias[threadIdx.x];
    __syncthreads();

    const int cg = threadIdx.x & 31;
    const int rg = threadIdx.x >> 5;
    const float4 bb = ((const float4*)sB)[cg];
    constexpr int K4 = K / 4;

    const float4* sWv  = (const float4*)sW;
    const float4* sInv = (const float4*)sIn;

    for (int tile = blockIdx.x; tile < ntiles; tile += gridDim.x) {
        const int base = tile * 64;

        // Stage 64 input rows (row-guarded for the 100000 % 64 tail)
        const float4* srcv = (const float4*)(A + (size_t)base * K);
        for (int i = threadIdx.x; i < 64 * K4; i += 256) {
            int row = base + i / K4;
            ((float4*)sIn)[i] = (row < NN) ? __ldg(&srcv[i]) : make_float4(0.f, 0.f, 0.f, 0.f);
        }
        __syncthreads();

        float acc[8][4];
        #pragma unroll
        for (int r = 0; r < 8; r++)
            #pragma unroll
            for (int c = 0; c < 4; c++) acc[r][c] = 0.f;

        #pragma unroll 2
        for (int k4 = 0; k4 < K4; k4++) {
            float4 in[8];
            #pragma unroll
            for (int r = 0; r < 8; r++)
                in[r] = sInv[(rg * 8 + r) * K4 + k4];   // broadcast within warp

            #pragma unroll
            for (int kk = 0; kk < 4; kk++) {
                float4 w = sWv[(k4 * 4 + kk) * 32 + cg];
                #pragma unroll
                for (int r = 0; r < 8; r++) {
                    float iv = (kk == 0) ? in[r].x : (kk == 1) ? in[r].y
                             : (kk == 2) ? in[r].z : in[r].w;
                    acc[r][0] += iv * w.x;
                    acc[r][1] += iv * w.y;
                    acc[r][2] += iv * w.z;
                    acc[r][3] += iv * w.w;
                }
            }
        }

        #pragma unroll
        for (int r = 0; r < 8; r++) {
            int row = base + rg * 8 + r;
            if (row < NN) {
                float4 o;
                o.x = fmaxf(acc[r][0] + bb.x, 0.f);
                o.y = fmaxf(acc[r][1] + bb.y, 0.f);
                o.z = fmaxf(acc[r][2] + bb.z, 0.f);
                o.w = fmaxf(acc[r][3] + bb.w, 0.f);
                ((float4*)(out + (size_t)row * 128))[cg] = o;
            }
        }
        __syncthreads();  // before next tile overwrites sIn
    }
}

// ---------------------------------------------------------------------------
__global__ void zero_pool() {
    int t = threadIdx.x;
    if (t < GG) { g_gsum[t] = 0.f; g_gcnt[t] = 0.f; }
}

// ---------------------------------------------------------------------------
// Pool: per-node dot(h2[i], Wfc) scattered into per-graph sums (linearity of
// mean-pool + FC). One warp per node. batch is INT32.
// ---------------------------------------------------------------------------
__global__ void pool_dot(const float* __restrict__ h,
                         const float* __restrict__ Wfc,
                         const int* __restrict__ batch) {
    __shared__ float sw[128];
    if (threadIdx.x < 128) sw[threadIdx.x] = Wfc[threadIdx.x];
    __syncthreads();
    int gw    = (blockIdx.x * blockDim.x + threadIdx.x) >> 5;
    int lane  = threadIdx.x & 31;
    int nwarp = (gridDim.x * blockDim.x) >> 5;
    for (int node = gw; node < NN; node += nwarp) {
        float4 v = ((const float4*)(h + (size_t)node * 128))[lane];
        float4 w = ((const float4*)sw)[lane];
        float p = v.x * w.x + v.y * w.y + v.z * w.z + v.w * w.w;
        #pragma unroll
        for (int o = 16; o > 0; o >>= 1) p += __shfl_down_sync(0xffffffffu, p, o);
        if (lane == 0) {
            int b = __ldg(&batch[node]);
            atomicAdd(&g_gsum[b], p);
            atomicAdd(&g_gcnt[b], 1.0f);
        }
    }
}

__global__ void finalize(float* __restrict__ out, const float* __restrict__ bfc) {
    int t = threadIdx.x;
    if (t < GG) out[t] = g_gsum[t] / fmaxf(g_gcnt[t], 1.0f) + bfc[0];
}

// ---------------------------------------------------------------------------
extern "C" void kernel_launch(void* const* d_in, const int* in_sizes, int n_in,
                              void* d_out, int out_size) {
    const float* x     = (const float*)d_in[0];
    const int*   ei    = (const int*)d_in[1];     // int32
    const int*   batch = (const int*)d_in[2];     // int32
    const float* W1a = (const float*)d_in[3];
    const float* b1a = (const float*)d_in[4];
    const float* W1b = (const float*)d_in[5];
    const float* b1b = (const float*)d_in[6];
    const float* W2a = (const float*)d_in[7];
    const float* b2a = (const float*)d_in[8];
    const float* W2b = (const float*)d_in[9];
    const float* b2b = (const float*)d_in[10];
    const float* Wfc = (const float*)d_in[11];
    const float* bfc = (const float*)d_in[12];
    float* out = (float*)d_out;

    const int* esrc = ei;
    const int* edst = ei + EE;

    float *agg, *tmp, *h1, *h2;
    cudaGetSymbolAddress((void**)&agg, g_agg);
    cudaGetSymbolAddress((void**)&tmp, g_tmp);
    cudaGetSymbolAddress((void**)&h1,  g_h1);
    cudaGetSymbolAddress((void**)&h2,  g_h2);

    const int smem64  = (64  * 128 + 64 * 64 ) * 4;   // 48 KB
    const int smem128 = (128 * 128 + 64 * 128) * 4;   // 96 KB
    cudaFuncSetAttribute(gemm_bias_relu<64>,  cudaFuncAttributeMaxDynamicSharedMemorySize, smem64);
    cudaFuncSetAttribute(gemm_bias_relu<128>, cudaFuncAttributeMaxDynamicSharedMemorySize, smem128);

    const int ntiles = (NN + 63) / 64;   // 1563 (last tile has 32 live rows)
    const int ggrid  = 296;              // ~2 blocks/SM persistent

    // ---- Layer 1 ----
    // agg := x  (so agg accumulates x + sum of neighbors)
    {
        int n4 = NN * DIN / 4;
        copy_f4<<<(n4 + 255) / 256, 256>>>((float4*)agg, (const float4*)x, n4);
    }
    {
        long long total = (long long)EE * (DIN / 4);
        int blocks = (int)((total + 255) / 256);
        scatter_add<DIN><<<blocks, 256>>>(x, esrc, edst, agg);
    }
    gemm_bias_relu<64> <<<ggrid, 256, smem64 >>>(agg, W1a, b1a, tmp, ntiles);
    gemm_bias_relu<128><<<ggrid, 256, smem128>>>(tmp, W1b, b1b, h1,  ntiles);

    // ---- Layer 2 ----
    {
        int n4 = NN * HID / 4;
        copy_f4<<<(n4 + 255) / 256, 256>>>((float4*)agg, (const float4*)h1, n4);
    }
    {
        long long total = (long long)EE * (HID / 4);
        int blocks = (int)((total + 255) / 256);
        scatter_add<HID><<<blocks, 256>>>(h1, esrc, edst, agg);
    }
    gemm_bias_relu<128><<<ggrid, 256, smem128>>>(agg, W2a, b2a, tmp, ntiles);
    gemm_bias_relu<128><<<ggrid, 256, smem128>>>(tmp, W2b, b2b, h2,  ntiles);

    // ---- Pool + FC ----
    zero_pool<<<1, 256>>>();
    pool_dot<<<512, 256>>>(h2, Wfc, batch);
    finalize<<<1, 256>>>(out, bfc);
}

// round 5
// speedup vs baseline: 1.1870x; 1.0379x over previous
#include <cuda_runtime.h>
#include <cuda_bf16.h>
#include <cstdint>

constexpr int NN  = 100000;   // nodes
constexpr int EE  = 1600000;  // edges
constexpr int GG  = 256;      // graphs
constexpr int DIN = 64;
constexpr int HID = 128;

// Scratch (device globals — no allocation allowed)
__device__ float g_agg[(size_t)NN * HID];
__device__ float g_tmp[(size_t)NN * HID];
__device__ float g_h1 [(size_t)NN * HID];
__device__ float g_h2 [(size_t)NN * HID];
__device__ float g_gsum[GG];
__device__ float g_gcnt[GG];
// CSR scratch
__device__ int g_cnt [NN];
__device__ int g_off [NN];
__device__ int g_pos [EE];
__device__ int g_ssrc[EE];

// ---------------------------------------------------------------------------
// CSR build: zero counters -> histogram (records slot) -> scan -> reorder
// ---------------------------------------------------------------------------
__global__ void zero_cnt() {
    int t = blockIdx.x * blockDim.x + threadIdx.x;
    if (t < NN) g_cnt[t] = 0;
}

__global__ void hist_kernel(const int* __restrict__ dst) {
    int e = blockIdx.x * blockDim.x + threadIdx.x;
    if (e < EE) g_pos[e] = atomicAdd(&g_cnt[__ldg(&dst[e])], 1);
}

constexpr int SCAN_T  = 1024;
constexpr int SCAN_CH = (NN + SCAN_T - 1) / SCAN_T;   // 98

__global__ void scan_kernel() {
    __shared__ int ssum[SCAN_T];
    int t = threadIdx.x;
    int base = t * SCAN_CH;
    int s = 0;
    #pragma unroll 4
    for (int i = 0; i < SCAN_CH; i++) {
        int j = base + i;
        if (j < NN) s += g_cnt[j];
    }
    ssum[t] = s;
    __syncthreads();
    // Hillis–Steele inclusive scan over 1024 partials
    for (int d = 1; d < SCAN_T; d <<= 1) {
        int v = (t >= d) ? ssum[t - d] : 0;
        __syncthreads();
        ssum[t] += v;
        __syncthreads();
    }
    int run = (t > 0) ? ssum[t - 1] : 0;   // exclusive base for this chunk
    for (int i = 0; i < SCAN_CH; i++) {
        int j = base + i;
        if (j < NN) { g_off[j] = run; run += g_cnt[j]; }
    }
}

__global__ void reorder_kernel(const int* __restrict__ src,
                               const int* __restrict__ dst) {
    int e = blockIdx.x * blockDim.x + threadIdx.x;
    if (e < EE) {
        int d = __ldg(&dst[e]);
        g_ssrc[g_off[d] + g_pos[e]] = __ldg(&src[e]);
    }
}

// ---------------------------------------------------------------------------
// Gather aggregation: agg[n] = x[n] + sum_{s in inNbr(n)} x[s]
// One warp per node. No atomics; coalesced row gathers (L2-resident tables).
// ---------------------------------------------------------------------------
__global__ void gather_agg_64(const float* __restrict__ x, float* __restrict__ agg) {
    int gw   = (blockIdx.x * blockDim.x + threadIdx.x) >> 5;
    int lane = threadIdx.x & 31;
    int nw   = (gridDim.x * blockDim.x) >> 5;
    for (int n = gw; n < NN; n += nw) {
        int lo = g_off[n], deg = g_cnt[n];
        float2 acc = __ldg((const float2*)(x + (size_t)n * 64) + lane);
        int i = 0;
        for (; i + 1 < deg; i += 2) {
            int s0 = __ldg(&g_ssrc[lo + i]);
            int s1 = __ldg(&g_ssrc[lo + i + 1]);
            float2 v0 = __ldg((const float2*)(x + (size_t)s0 * 64) + lane);
            float2 v1 = __ldg((const float2*)(x + (size_t)s1 * 64) + lane);
            acc.x += v0.x; acc.y += v0.y;
            acc.x += v1.x; acc.y += v1.y;
        }
        if (i < deg) {
            int s = __ldg(&g_ssrc[lo + i]);
            float2 v = __ldg((const float2*)(x + (size_t)s * 64) + lane);
            acc.x += v.x; acc.y += v.y;
        }
        ((float2*)(agg + (size_t)n * 64))[lane] = acc;
    }
}

__global__ void gather_agg_128(const float* __restrict__ x, float* __restrict__ agg) {
    int gw   = (blockIdx.x * blockDim.x + threadIdx.x) >> 5;
    int lane = threadIdx.x & 31;
    int nw   = (gridDim.x * blockDim.x) >> 5;
    for (int n = gw; n < NN; n += nw) {
        int lo = g_off[n], deg = g_cnt[n];
        float4 acc = __ldg((const float4*)(x + (size_t)n * 128) + lane);
        int i = 0;
        for (; i + 1 < deg; i += 2) {
            int s0 = __ldg(&g_ssrc[lo + i]);
            int s1 = __ldg(&g_ssrc[lo + i + 1]);
            float4 v0 = __ldg((const float4*)(x + (size_t)s0 * 128) + lane);
            float4 v1 = __ldg((const float4*)(x + (size_t)s1 * 128) + lane);
            acc.x += v0.x; acc.y += v0.y; acc.z += v0.z; acc.w += v0.w;
            acc.x += v1.x; acc.y += v1.y; acc.z += v1.z; acc.w += v1.w;
        }
        if (i < deg) {
            int s = __ldg(&g_ssrc[lo + i]);
            float4 v = __ldg((const float4*)(x + (size_t)s * 128) + lane);
            acc.x += v.x; acc.y += v.y; acc.z += v.z; acc.w += v.w;
        }
        ((float4*)(agg + (size_t)n * 128))[lane] = acc;
    }
}

// ---------------------------------------------------------------------------
// Fused GEMM + bias + ReLU:  out[N,128] = relu(A[N,K] @ W[K,128] + b)
// 128 threads/block. Tile = 64 rows x 128 cols. Thread tile = 8 rows x 8 cols.
//   cg = tid & 15  -> cols [8cg, 8cg+8)  (two LDS.128 on W)
//   rg = tid >> 4  -> rows [8rg, 8rg+8)  (broadcast LDS.128 on inputs)
// Per k4-step/thread: 16 LDS.128 per 256 FMAs. Persistent blocks, W in SMEM.
// ---------------------------------------------------------------------------
template <int K>
__global__ __launch_bounds__(128, 2) void gemm_bias_relu(
    const float* __restrict__ A, const float* __restrict__ W,
    const float* __restrict__ bias, float* __restrict__ out, int ntiles)
{
    extern __shared__ float smem[];
    float* sW  = smem;                  // K*128 floats
    float* sIn = smem + K * 128;        // 64*K floats
    __shared__ float sB[128];

    for (int i = threadIdx.x; i < K * 32; i += 128)
        ((float4*)sW)[i] = __ldg(&((const float4*)W)[i]);
    if (threadIdx.x < 128) sB[threadIdx.x] = bias[threadIdx.x];
    __syncthreads();

    const int cg = threadIdx.x & 15;
    const int rg = threadIdx.x >> 4;
    const float4 b0 = ((const float4*)sB)[2 * cg];
    const float4 b1 = ((const float4*)sB)[2 * cg + 1];
    constexpr int K4 = K / 4;

    const float4* sWv  = (const float4*)sW;
    const float4* sInv = (const float4*)sIn;

    for (int tile = blockIdx.x; tile < ntiles; tile += gridDim.x) {
        const int base = tile * 64;

        // Stage 64 input rows (row-guarded for the 100000 % 64 tail)
        const float4* srcv = (const float4*)(A + (size_t)base * K);
        for (int i = threadIdx.x; i < 64 * K4; i += 128) {
            int row = base + i / K4;
            ((float4*)sIn)[i] = (row < NN) ? __ldg(&srcv[i]) : make_float4(0.f, 0.f, 0.f, 0.f);
        }
        __syncthreads();

        float acc[8][8];
        #pragma unroll
        for (int r = 0; r < 8; r++)
            #pragma unroll
            for (int c = 0; c < 8; c++) acc[r][c] = 0.f;

        #pragma unroll 2
        for (int k4 = 0; k4 < K4; k4++) {
            float4 in[8];
            #pragma unroll
            for (int r = 0; r < 8; r++)
                in[r] = sInv[(rg * 8 + r) * K4 + k4];

            #pragma unroll
            for (int kk = 0; kk < 4; kk++) {
                float4 wa = sWv[(k4 * 4 + kk) * 32 + 2 * cg];
                float4 wb = sWv[(k4 * 4 + kk) * 32 + 2 * cg + 1];
                #pragma unroll
                for (int r = 0; r < 8; r++) {
                    float iv = (kk == 0) ? in[r].x : (kk == 1) ? in[r].y
                             : (kk == 2) ? in[r].z : in[r].w;
                    acc[r][0] += iv * wa.x;
                    acc[r][1] += iv * wa.y;
                    acc[r][2] += iv * wa.z;
                    acc[r][3] += iv * wa.w;
                    acc[r][4] += iv * wb.x;
                    acc[r][5] += iv * wb.y;
                    acc[r][6] += iv * wb.z;
                    acc[r][7] += iv * wb.w;
                }
            }
        }

        #pragma unroll
        for (int r = 0; r < 8; r++) {
            int row = base + rg * 8 + r;
            if (row < NN) {
                float4 o0, o1;
                o0.x = fmaxf(acc[r][0] + b0.x, 0.f);
                o0.y = fmaxf(acc[r][1] + b0.y, 0.f);
                o0.z = fmaxf(acc[r][2] + b0.z, 0.f);
                o0.w = fmaxf(acc[r][3] + b0.w, 0.f);
                o1.x = fmaxf(acc[r][4] + b1.x, 0.f);
                o1.y = fmaxf(acc[r][5] + b1.y, 0.f);
                o1.z = fmaxf(acc[r][6] + b1.z, 0.f);
                o1.w = fmaxf(acc[r][7] + b1.w, 0.f);
                float4* op = (float4*)(out + (size_t)row * 128);
                op[2 * cg]     = o0;
                op[2 * cg + 1] = o1;
            }
        }
        __syncthreads();
    }
}

// ---------------------------------------------------------------------------
__global__ void zero_pool() {
    int t = threadIdx.x;
    if (t < GG) { g_gsum[t] = 0.f; g_gcnt[t] = 0.f; }
}

// Pool: per-node dot(h2[i], Wfc) scattered into per-graph sums.
__global__ void pool_dot(const float* __restrict__ h,
                         const float* __restrict__ Wfc,
                         const int* __restrict__ batch) {
    __shared__ float sw[128];
    if (threadIdx.x < 128) sw[threadIdx.x] = Wfc[threadIdx.x];
    __syncthreads();
    int gw    = (blockIdx.x * blockDim.x + threadIdx.x) >> 5;
    int lane  = threadIdx.x & 31;
    int nwarp = (gridDim.x * blockDim.x) >> 5;
    for (int node = gw; node < NN; node += nwarp) {
        float4 v = ((const float4*)(h + (size_t)node * 128))[lane];
        float4 w = ((const float4*)sw)[lane];
        float p = v.x * w.x + v.y * w.y + v.z * w.z + v.w * w.w;
        #pragma unroll
        for (int o = 16; o > 0; o >>= 1) p += __shfl_down_sync(0xffffffffu, p, o);
        if (lane == 0) {
            int b = __ldg(&batch[node]);
            atomicAdd(&g_gsum[b], p);
            atomicAdd(&g_gcnt[b], 1.0f);
        }
    }
}

__global__ void finalize(float* __restrict__ out, const float* __restrict__ bfc) {
    int t = threadIdx.x;
    if (t < GG) out[t] = g_gsum[t] / fmaxf(g_gcnt[t], 1.0f) + bfc[0];
}

// ---------------------------------------------------------------------------
extern "C" void kernel_launch(void* const* d_in, const int* in_sizes, int n_in,
                              void* d_out, int out_size) {
    const float* x     = (const float*)d_in[0];
    const int*   ei    = (const int*)d_in[1];     // int32
    const int*   batch = (const int*)d_in[2];     // int32
    const float* W1a = (const float*)d_in[3];
    const float* b1a = (const float*)d_in[4];
    const float* W1b = (const float*)d_in[5];
    const float* b1b = (const float*)d_in[6];
    const float* W2a = (const float*)d_in[7];
    const float* b2a = (const float*)d_in[8];
    const float* W2b = (const float*)d_in[9];
    const float* b2b = (const float*)d_in[10];
    const float* Wfc = (const float*)d_in[11];
    const float* bfc = (const float*)d_in[12];
    float* out = (float*)d_out;

    const int* esrc = ei;
    const int* edst = ei + EE;

    float *agg, *tmp, *h1, *h2;
    cudaGetSymbolAddress((void**)&agg, g_agg);
    cudaGetSymbolAddress((void**)&tmp, g_tmp);
    cudaGetSymbolAddress((void**)&h1,  g_h1);
    cudaGetSymbolAddress((void**)&h2,  g_h2);

    const int smem64  = (64  * 128 + 64 * 64 ) * 4;   // 48 KB
    const int smem128 = (128 * 128 + 64 * 128) * 4;   // 96 KB
    cudaFuncSetAttribute(gemm_bias_relu<64>,  cudaFuncAttributeMaxDynamicSharedMemorySize, smem64);
    cudaFuncSetAttribute(gemm_bias_relu<128>, cudaFuncAttributeMaxDynamicSharedMemorySize, smem128);

    const int ntiles = (NN + 63) / 64;   // 1563
    const int ggrid  = 296;              // 2 blocks/SM persistent

    // ---- CSR build (per call; reused by both layers) ----
    zero_cnt<<<(NN + 255) / 256, 256>>>();
    hist_kernel<<<(EE + 255) / 256, 256>>>(edst);
    scan_kernel<<<1, SCAN_T>>>();
    reorder_kernel<<<(EE + 255) / 256, 256>>>(esrc, edst);

    // ---- Layer 1 ----
    gather_agg_64<<<1024, 256>>>(x, agg);
    gemm_bias_relu<64> <<<ggrid, 128, smem64 >>>(agg, W1a, b1a, tmp, ntiles);
    gemm_bias_relu<128><<<ggrid, 128, smem128>>>(tmp, W1b, b1b, h1,  ntiles);

    // ---- Layer 2 ----
    gather_agg_128<<<1024, 256>>>(h1, agg);
    gemm_bias_relu<128><<<ggrid, 128, smem128>>>(agg, W2a, b2a, tmp, ntiles);
    gemm_bias_relu<128><<<ggrid, 128, smem128>>>(tmp, W2b, b2b, h2,  ntiles);

    // ---- Pool + FC ----
    zero_pool<<<1, 256>>>();
    pool_dot<<<512, 256>>>(h2, Wfc, batch);
    finalize<<<1, 256>>>(out, bfc);
}

// round 8
// speedup vs baseline: 1.4584x; 1.2287x over previous
#include <cuda_runtime.h>
#include <cuda_bf16.h>
#include <cstdint>

constexpr int NN  = 100000;   // nodes
constexpr int EE  = 1600000;  // edges
constexpr int GG  = 256;      // graphs
constexpr int DIN = 64;
constexpr int HID = 128;

// Scratch (device globals — no allocation allowed)
__device__ float g_agg[(size_t)NN * HID];
__device__ float g_tmp[(size_t)NN * HID];
__device__ float g_h1 [(size_t)NN * HID];
__device__ float g_h2 [(size_t)NN * HID];
__device__ float g_gsum[GG];
__device__ float g_gcnt[GG];
// CSR scratch
__device__ int g_cnt [NN];
__device__ int g_off [NN];
__device__ int g_pos [EE];
__device__ int g_ssrc[EE];

// ===========================================================================
// Warp-level tensor-core primitives (base ISA: valid on target sm_100)
// ===========================================================================
__device__ __forceinline__ uint32_t smem_u32(const void* p) {
    uint32_t a;
    asm("{ .reg .u64 t; cvta.to.shared.u64 t, %1; cvt.u32.u64 %0, t; }" : "=r"(a) : "l"(p));
    return a;
}

__device__ __forceinline__ void ldmatrix_x4(uint32_t* r, uint32_t addr) {
    asm volatile("ldmatrix.sync.aligned.m8n8.x4.shared.b16 {%0,%1,%2,%3}, [%4];"
                 : "=r"(r[0]), "=r"(r[1]), "=r"(r[2]), "=r"(r[3]) : "r"(addr));
}
__device__ __forceinline__ void ldmatrix_x2(uint32_t* r, uint32_t addr) {
    asm volatile("ldmatrix.sync.aligned.m8n8.x2.shared.b16 {%0,%1}, [%2];"
                 : "=r"(r[0]), "=r"(r[1]) : "r"(addr));
}

// D(16x8,f32) += A(16x16,bf16,row) * B(16x8,bf16,col)
__device__ __forceinline__ void mma_16816(float* d, const uint32_t* a, const uint32_t* b) {
    asm volatile(
        "mma.sync.aligned.m16n8k16.row.col.f32.bf16.bf16.f32 "
        "{%0,%1,%2,%3}, {%4,%5,%6,%7}, {%8,%9}, {%0,%1,%2,%3};"
        : "+f"(d[0]), "+f"(d[1]), "+f"(d[2]), "+f"(d[3])
        : "r"(a[0]), "r"(a[1]), "r"(a[2]), "r"(a[3]), "r"(b[0]), "r"(b[1]));
}

__device__ __forceinline__ uint32_t pack_bf16x2(float x, float y) {
    __nv_bfloat16 bx = __float2bfloat16(x), by = __float2bfloat16(y);
    return ((uint32_t)__bfloat16_as_ushort(by) << 16) | __bfloat16_as_ushort(bx);
}

// ===========================================================================
// CSR build: zero -> histogram -> scan -> reorder
// ===========================================================================
__global__ void zero_cnt() {
    int t = blockIdx.x * blockDim.x + threadIdx.x;
    if (t < NN) g_cnt[t] = 0;
}

__global__ void hist_kernel(const int* __restrict__ dst) {
    int e = blockIdx.x * blockDim.x + threadIdx.x;
    if (e < EE) g_pos[e] = atomicAdd(&g_cnt[__ldg(&dst[e])], 1);
}

constexpr int SCAN_T  = 1024;
constexpr int SCAN_CH = (NN + SCAN_T - 1) / SCAN_T;   // 98

__global__ void scan_kernel() {
    __shared__ int ssum[SCAN_T];
    int t = threadIdx.x;
    int base = t * SCAN_CH;
    int s = 0;
    #pragma unroll 4
    for (int i = 0; i < SCAN_CH; i++) {
        int j = base + i;
        if (j < NN) s += g_cnt[j];
    }
    ssum[t] = s;
    __syncthreads();
    for (int d = 1; d < SCAN_T; d <<= 1) {
        int v = (t >= d) ? ssum[t - d] : 0;
        __syncthreads();
        ssum[t] += v;
        __syncthreads();
    }
    int run = (t > 0) ? ssum[t - 1] : 0;
    for (int i = 0; i < SCAN_CH; i++) {
        int j = base + i;
        if (j < NN) { g_off[j] = run; run += g_cnt[j]; }
    }
}

__global__ void reorder_kernel(const int* __restrict__ src,
                               const int* __restrict__ dst) {
    int e = blockIdx.x * blockDim.x + threadIdx.x;
    if (e < EE) {
        int d = __ldg(&dst[e]);
        g_ssrc[g_off[d] + g_pos[e]] = __ldg(&src[e]);
    }
}

// ===========================================================================
// Gather aggregation: agg[n] = x[n] + sum_{s in inNbr(n)} x[s]
// ===========================================================================
__global__ void gather_agg_64(const float* __restrict__ x, float* __restrict__ agg) {
    int gw   = (blockIdx.x * blockDim.x + threadIdx.x) >> 5;
    int lane = threadIdx.x & 31;
    int nw   = (gridDim.x * blockDim.x) >> 5;
    for (int n = gw; n < NN; n += nw) {
        int lo = g_off[n], deg = g_cnt[n];
        float2 acc = __ldg((const float2*)(x + (size_t)n * 64) + lane);
        int i = 0;
        for (; i + 1 < deg; i += 2) {
            int s0 = __ldg(&g_ssrc[lo + i]);
            int s1 = __ldg(&g_ssrc[lo + i + 1]);
            float2 v0 = __ldg((const float2*)(x + (size_t)s0 * 64) + lane);
            float2 v1 = __ldg((const float2*)(x + (size_t)s1 * 64) + lane);
            acc.x += v0.x; acc.y += v0.y;
            acc.x += v1.x; acc.y += v1.y;
        }
        if (i < deg) {
            int s = __ldg(&g_ssrc[lo + i]);
            float2 v = __ldg((const float2*)(x + (size_t)s * 64) + lane);
            acc.x += v.x; acc.y += v.y;
        }
        ((float2*)(agg + (size_t)n * 64))[lane] = acc;
    }
}

__global__ void gather_agg_128(const float* __restrict__ x, float* __restrict__ agg) {
    int gw   = (blockIdx.x * blockDim.x + threadIdx.x) >> 5;
    int lane = threadIdx.x & 31;
    int nw   = (gridDim.x * blockDim.x) >> 5;
    for (int n = gw; n < NN; n += nw) {
        int lo = g_off[n], deg = g_cnt[n];
        float4 acc = __ldg((const float4*)(x + (size_t)n * 128) + lane);
        int i = 0;
        for (; i + 1 < deg; i += 2) {
            int s0 = __ldg(&g_ssrc[lo + i]);
            int s1 = __ldg(&g_ssrc[lo + i + 1]);
            float4 v0 = __ldg((const float4*)(x + (size_t)s0 * 128) + lane);
            float4 v1 = __ldg((const float4*)(x + (size_t)s1 * 128) + lane);
            acc.x += v0.x; acc.y += v0.y; acc.z += v0.z; acc.w += v0.w;
            acc.x += v1.x; acc.y += v1.y; acc.z += v1.z; acc.w += v1.w;
        }
        if (i < deg) {
            int s = __ldg(&g_ssrc[lo + i]);
            float4 v = __ldg((const float4*)(x + (size_t)s * 128) + lane);
            acc.x += v.x; acc.y += v.y; acc.z += v.z; acc.w += v.w;
        }
        ((float4*)(agg + (size_t)n * 128))[lane] = acc;
    }
}

// ===========================================================================
// Tensor-core GEMM + bias + ReLU:  out[N,128] = relu(A[N,K] @ W[K,128] + b)
//
// mma.sync m16n8k16 bf16 with split accumulation:
//   D = A_hi*B_hi + A_hi*B_lo + A_lo*B_hi    (fp32 regs; error ~1.5e-5)
//
// 256 threads, persistent. Warp w owns out cols [16w,16w+16); its B fragments
// (W^T hi/lo, all k-chunks) live in registers for the whole kernel.
// Per 128-row tile: stage A hi/lo to padded smem, ldmatrix + mma, epilogue
// straight from accumulator registers (bias+ReLU, float2 stores).
// ===========================================================================
template <int K>
__global__ __launch_bounds__(256, 1)
void gemm_mma(const float* __restrict__ A, const float* __restrict__ W,
              const float* __restrict__ bias, float* __restrict__ out, int ntiles)
{
    constexpr int KCH = K / 16;          // k-chunks
    constexpr int RSB = K * 2 + 16;      // smem row stride bytes (conflict-free)
    constexpr int K4  = K / 4;
    extern __shared__ __align__(16) char smem[];
    char* sHi = smem;                    // 128 x RSB
    char* sLo = smem + 128 * RSB;        // 128 x RSB

    const int tid  = threadIdx.x;
    const int wid  = tid >> 5;
    const int lane = tid & 31;
    const uint32_t uHi = smem_u32(sHi);
    const uint32_t uLo = smem_u32(sLo);

    // ---- Stage B = W^T hi/lo into smem ([n][k] row-major, padded) ----
    for (int i = tid; i < K * 128; i += 256) {
        int k = i >> 7, n = i & 127;                 // coalesced read of W[k][n]
        float w = __ldg(&W[i]);
        __nv_bfloat16 hi = __float2bfloat16(w);
        __nv_bfloat16 lo = __float2bfloat16(w - __bfloat162float(hi));
        *(__nv_bfloat16*)(sHi + n * RSB + k * 2) = hi;
        *(__nv_bfloat16*)(sLo + n * RSB + k * 2) = lo;
    }
    __syncthreads();

    // ---- Extract persistent B fragments (warp w: n-tiles at 16w, 16w+8) ----
    uint32_t Bhi[KCH][2][2], Blo[KCH][2][2];
    {
        int r   = lane & 7;
        int mat = (lane >> 3) & 1;                   // lanes 0-7: mat0, 8-15: mat1
        #pragma unroll
        for (int j = 0; j < 2; j++) {
            int n = wid * 16 + j * 8 + r;
            #pragma unroll
            for (int c = 0; c < KCH; c++) {
                uint32_t off = (uint32_t)n * RSB + c * 32 + mat * 16;
                ldmatrix_x2(Bhi[c][j], uHi + off);
                ldmatrix_x2(Blo[c][j], uLo + off);
            }
        }
    }
    __syncthreads();

    // Per-thread bias (cols fixed for the whole kernel)
    const int c0 = wid * 16 + (lane & 3) * 2;
    const float bs00 = __ldg(&bias[c0]),     bs01 = __ldg(&bias[c0 + 1]);
    const float bs10 = __ldg(&bias[c0 + 8]), bs11 = __ldg(&bias[c0 + 9]);

    // ldmatrix.x4 lane address pattern for A (row-major 16x16 -> a0..a3)
    const int ar = (lane & 7) + ((lane & 8) ? 8 : 0);   // row within m-tile
    const int ak = (lane & 16) ? 16 : 0;                // k-byte offset

    for (int tile = blockIdx.x; tile < ntiles; tile += gridDim.x) {
        const int base = tile * 128;

        // ---- Stage A tile hi/lo ----
        const float4* Av = (const float4*)(A + (size_t)base * K);
        for (int i = tid; i < 128 * K4; i += 256) {
            int row = i / K4;
            int k   = (i - row * K4) * 4;
            float4 v = (base + row < NN) ? __ldg(&Av[i]) : make_float4(0.f, 0.f, 0.f, 0.f);
            __nv_bfloat16 h0 = __float2bfloat16(v.x), h1 = __float2bfloat16(v.y);
            __nv_bfloat16 h2 = __float2bfloat16(v.z), h3 = __float2bfloat16(v.w);
            uint2 hp, lp;
            hp.x = ((uint32_t)__bfloat16_as_ushort(h1) << 16) | __bfloat16_as_ushort(h0);
            hp.y = ((uint32_t)__bfloat16_as_ushort(h3) << 16) | __bfloat16_as_ushort(h2);
            lp.x = pack_bf16x2(v.x - __bfloat162float(h0), v.y - __bfloat162float(h1));
            lp.y = pack_bf16x2(v.z - __bfloat162float(h2), v.w - __bfloat162float(h3));
            *(uint2*)(sHi + row * RSB + k * 2) = hp;
            *(uint2*)(sLo + row * RSB + k * 2) = lp;
        }
        __syncthreads();

        float acc[8][2][4];
        #pragma unroll
        for (int mt = 0; mt < 8; mt++)
            #pragma unroll
            for (int j = 0; j < 2; j++)
                #pragma unroll
                for (int q = 0; q < 4; q++) acc[mt][j][q] = 0.f;

        #pragma unroll
        for (int mt = 0; mt < 8; mt++) {
            uint32_t arow = (uint32_t)(mt * 16 + ar) * RSB + ak;
            #pragma unroll
            for (int c = 0; c < KCH; c++) {
                uint32_t ahi[4], alo[4];
                ldmatrix_x4(ahi, uHi + arow + c * 32);
                ldmatrix_x4(alo, uLo + arow + c * 32);
                #pragma unroll
                for (int j = 0; j < 2; j++) {
                    mma_16816(acc[mt][j], ahi, Bhi[c][j]);
                    mma_16816(acc[mt][j], ahi, Blo[c][j]);
                    mma_16816(acc[mt][j], alo, Bhi[c][j]);
                }
            }
        }

        // ---- Epilogue: bias + ReLU from registers, float2 stores ----
        #pragma unroll
        for (int mt = 0; mt < 8; mt++) {
            int r0 = base + mt * 16 + (lane >> 2);
            int r1 = r0 + 8;
            #pragma unroll
            for (int j = 0; j < 2; j++) {
                float bx = j ? bs10 : bs00;
                float by = j ? bs11 : bs01;
                int col = wid * 16 + j * 8 + (lane & 3) * 2;
                if (r0 < NN) {
                    float2 o;
                    o.x = fmaxf(acc[mt][j][0] + bx, 0.f);
                    o.y = fmaxf(acc[mt][j][1] + by, 0.f);
                    *(float2*)(out + (size_t)r0 * 128 + col) = o;
                }
                if (r1 < NN) {
                    float2 o;
                    o.x = fmaxf(acc[mt][j][2] + bx, 0.f);
                    o.y = fmaxf(acc[mt][j][3] + by, 0.f);
                    *(float2*)(out + (size_t)r1 * 128 + col) = o;
                }
            }
        }
        __syncthreads();   // A smem free before next tile
    }
}

// ===========================================================================
__global__ void zero_pool() {
    int t = threadIdx.x;
    if (t < GG) { g_gsum[t] = 0.f; g_gcnt[t] = 0.f; }
}

__global__ void pool_dot(const float* __restrict__ h,
                         const float* __restrict__ Wfc,
                         const int* __restrict__ batch) {
    __shared__ float sw[128];
    if (threadIdx.x < 128) sw[threadIdx.x] = Wfc[threadIdx.x];
    __syncthreads();
    int gw    = (blockIdx.x * blockDim.x + threadIdx.x) >> 5;
    int lane  = threadIdx.x & 31;
    int nwarp = (gridDim.x * blockDim.x) >> 5;
    for (int node = gw; node < NN; node += nwarp) {
        float4 v = ((const float4*)(h + (size_t)node * 128))[lane];
        float4 w = ((const float4*)sw)[lane];
        float p = v.x * w.x + v.y * w.y + v.z * w.z + v.w * w.w;
        #pragma unroll
        for (int o = 16; o > 0; o >>= 1) p += __shfl_down_sync(0xffffffffu, p, o);
        if (lane == 0) {
            int b = __ldg(&batch[node]);
            atomicAdd(&g_gsum[b], p);
            atomicAdd(&g_gcnt[b], 1.0f);
        }
    }
}

__global__ void finalize(float* __restrict__ out, const float* __restrict__ bfc) {
    int t = threadIdx.x;
    if (t < GG) out[t] = g_gsum[t] / fmaxf(g_gcnt[t], 1.0f) + bfc[0];
}

// ===========================================================================
extern "C" void kernel_launch(void* const* d_in, const int* in_sizes, int n_in,
                              void* d_out, int out_size) {
    const float* x     = (const float*)d_in[0];
    const int*   ei    = (const int*)d_in[1];     // int32
    const int*   batch = (const int*)d_in[2];     // int32
    const float* W1a = (const float*)d_in[3];
    const float* b1a = (const float*)d_in[4];
    const float* W1b = (const float*)d_in[5];
    const float* b1b = (const float*)d_in[6];
    const float* W2a = (const float*)d_in[7];
    const float* b2a = (const float*)d_in[8];
    const float* W2b = (const float*)d_in[9];
    const float* b2b = (const float*)d_in[10];
    const float* Wfc = (const float*)d_in[11];
    const float* bfc = (const float*)d_in[12];
    float* out = (float*)d_out;

    const int* esrc = ei;
    const int* edst = ei + EE;

    float *agg, *tmp, *h1, *h2;
    cudaGetSymbolAddress((void**)&agg, g_agg);
    cudaGetSymbolAddress((void**)&tmp, g_tmp);
    cudaGetSymbolAddress((void**)&h1,  g_h1);
    cudaGetSymbolAddress((void**)&h2,  g_h2);

    const int smemM64  = 2 * 128 * (64  * 2 + 16);   // 36,864 B
    const int smemM128 = 2 * 128 * (128 * 2 + 16);   // 69,632 B
    cudaFuncSetAttribute(gemm_mma<64>,  cudaFuncAttributeMaxDynamicSharedMemorySize, smemM64);
    cudaFuncSetAttribute(gemm_mma<128>, cudaFuncAttributeMaxDynamicSharedMemorySize, smemM128);

    const int ntiles = (NN + 127) / 128;   // 782

    // ---- CSR build (per call; reused by both layers) ----
    zero_cnt<<<(NN + 255) / 256, 256>>>();
    hist_kernel<<<(EE + 255) / 256, 256>>>(edst);
    scan_kernel<<<1, SCAN_T>>>();
    reorder_kernel<<<(EE + 255) / 256, 256>>>(esrc, edst);

    // ---- Layer 1 ----
    gather_agg_64<<<1024, 256>>>(x, agg);
    gemm_mma<64> <<<296, 256, smemM64 >>>(agg, W1a, b1a, tmp, ntiles);
    gemm_mma<128><<<148, 256, smemM128>>>(tmp, W1b, b1b, h1,  ntiles);

    // ---- Layer 2 ----
    gather_agg_128<<<1024, 256>>>(h1, agg);
    gemm_mma<128><<<148, 256, smemM128>>>(agg, W2a, b2a, tmp, ntiles);
    gemm_mma<128><<<148, 256, smemM128>>>(tmp, W2b, b2b, h2,  ntiles);

    // ---- Pool + FC ----
    zero_pool<<<1, 256>>>();
    pool_dot<<<512, 256>>>(h2, Wfc, batch);
    finalize<<<1, 256>>>(out, bfc);
}